// round 15
// baseline (speedup 1.0000x reference)
#include <cuda_runtime.h>
#include <cuda_bf16.h>
#include <math.h>
#include <stdint.h>

#define NB 128
#define NT 2048
#define NH 200
#define NH4 800
#define NSTEP 5

// ---- scratch ----
__device__ float g_qproj[NB * NH];
__device__ float g_hpre[NB * NH4];
__device__ float g_ctxpart[NB * 16 * NH];   // per-tile ctx partials
__device__ float g_denpart[NB * 16];        // per-tile denom partials

__device__ __forceinline__ float sigm(float x) { return 1.f / (1.f + expf(-x)); }

__device__ __forceinline__ float tanh_mufu(float x) {
    float m = x * 2.8853900817779268f;   // 2*log2(e)
    float e; asm("ex2.approx.ftz.f32 %0, %1;" : "=f"(e) : "f"(m));
    float d = 1.f + e;
    float rc; asm("rcp.approx.ftz.f32 %0, %1;" : "=f"(rc) : "f"(d));
    return fmaf(-2.f, rc, 1.f);
}

__device__ __forceinline__ uint32_t pack_bf2(float lo, float hi) {
    uint32_t r;
    asm("cvt.rn.bf16x2.f32 %0, %1, %2;" : "=r"(r) : "f"(hi), "f"(lo));
    return r;
}
__device__ __forceinline__ float warp_sum(float s) {
    #pragma unroll
    for (int o = 16; o; o >>= 1) s += __shfl_xor_sync(0xffffffffu, s, o);
    return s;
}
__device__ __forceinline__ uint32_t s2u(const void* p) {
    return (uint32_t)__cvta_generic_to_shared(p);
}

// no-op kernel (trailing): keeps 4 launches/call so ncu capture (skip 5)
// lands on call-2's k_scores.
__global__ void k_nop() {}

// ============================================================================
// K1: q_proj / h_pre gemv, weight-reuse tiling: grid(40, 8), 256 threads.
// ============================================================================
__global__ __launch_bounds__(256) void k_pre(
    const float* __restrict__ h0, const float* __restrict__ Wa,
    const float* __restrict__ ba, const float* __restrict__ Whh,
    const float* __restrict__ bhh) {
    const int oc = blockIdx.x, bg = blockIdx.y, tid = threadIdx.x;
    const int w = tid >> 5, l = tid & 31;
    __shared__ float hs[16 * NH];
    for (int i = tid; i < 16 * NH; i += 256)
        hs[i] = h0[(bg * 16 + i / NH) * NH + (i % NH)];
    __syncthreads();
    #pragma unroll 1
    for (int ol = 0; ol < 25; ol++) {
        const int o = oc * 25 + ol;
        const float* row = (o < NH) ? (Wa + o * NH) : (Whh + (o - NH) * NH);
        #pragma unroll
        for (int rep = 0; rep < 2; rep++) {
            const int bl = w * 2 + rep;
            const float* h = hs + bl * NH;
            float s = 0.f;
            #pragma unroll
            for (int k = l; k < NH; k += 32) s = fmaf(h[k], row[k], s);
            s = warp_sum(s);
            if (l == 0) {
                const int b = bg * 16 + bl;
                if (o < NH) g_qproj[b * NH + o] = s + ba[o];
                else        g_hpre[b * NH4 + (o - NH)] = s + bhh[o - NH];
            }
        }
    }
}

// ============================================================================
// K2: scores GEMM + fused softmax/ctx partials.
//   MT=128, 512 threads (8 m-warps x 2 n-warps).
//   THIS ROUND: 3 accumulator chains per jt (kt mod 3; depths 5/4/4) to cut
//   HMMA RAW stalls; B ring 2-deep to keep regs flat (~124, no spill).
// ============================================================================
#define NCTA 148
#define MT 128
#define NP 224
#define ASTR 216
#define AW 108
#define BS_U32 (NP * AW)
#define AS_U32 (MT * AW)
#define NTILES (NB * 16)
#define SMEM_SC ((BS_U32 + 2 * AS_U32) * 4 + 2 * NP * 8 + 256 * 4 + 128 * 4 + 4 * NH * 4 + 64)

__device__ __forceinline__ void stage_tile(
    uint32_t* __restrict__ dst, float2* __restrict__ vqd,
    const float* __restrict__ enc, const float* __restrict__ Va,
    const float* __restrict__ bua, int b, int trow, int tid) {
    const float* eb = enc + ((size_t)b * NT + trow) * NH;
    #pragma unroll
    for (int half = 0; half < 2; half++) {
        const int nb = half ? 13 : 14;
        const int base = half * 14;
        float2 f[14];
        #pragma unroll
        for (int i = 0; i < 14; i++) {
            if (i < nb) {
                int idx = tid + ((base + i) << 9);
                int r = idx / AW, p = idx - r * AW;
                f[i] = make_float2(0.f, 0.f);
                if (p < 100) f[i] = *(const float2*)(eb + r * NH + 2 * p);
            }
        }
        #pragma unroll
        for (int i = 0; i < 14; i++) {
            if (i < nb) {
                int idx = tid + ((base + i) << 9);
                dst[idx] = pack_bf2(f[i].x, f[i].y);
            }
        }
    }
    if (tid < NP) {
        float vv = 0.f, qq = 0.f;
        if (tid < NH) { vv = Va[tid]; qq = g_qproj[b * NH + tid] + bua[tid]; }
        vqd[tid] = make_float2(vv, qq);
    }
}

__global__ __launch_bounds__(512, 1) void k_scores(
    const float* __restrict__ enc, const float* __restrict__ Ua,
    const float* __restrict__ bua, const float* __restrict__ Va,
    const float* __restrict__ bva) {
    extern __shared__ uint32_t sm32[];
    uint32_t* Bs  = sm32;
    uint32_t* As0 = Bs + BS_U32;
    uint32_t* As1 = As0 + AS_U32;
    float2*   vq  = (float2*)(As1 + AS_U32);
    float*    srow = (float*)(vq + 2 * NP);     // [2][128]
    float*    pbuf = srow + 256;                // [128]
    float*    cpart = pbuf + 128;               // [4][200]

    const int tid = threadIdx.x, l = tid & 31, wid = tid >> 5;
    const int mw = wid & 7, nw = wid >> 3;      // 8 m-warps x 2 n-warps
    const int bid = blockIdx.x;
    const float bv0 = bva[0];
    const int njt = (nw == 0) ? 13 : 12;
    const int ncol = nw ? 104 : 0;

    for (int i = tid; i < BS_U32; i += 512) Bs[i] = 0;
    __syncthreads();
    for (int i = tid; i < NH * 100; i += 512) {
        int n = i / 100, k2 = i - n * 100;
        float2 f = *(const float2*)(Ua + n * NH + 2 * k2);
        Bs[n * AW + k2] = pack_bf2(f.x, f.y);
    }

    const int ntile = (NTILES - bid + NCTA - 1) / NCTA;
    {
        int gt = bid;
        stage_tile(As0, vq, enc, Va, bua, gt >> 4, (gt & 15) << 7, tid);
    }
    __syncthreads();

    const uint32_t bbase4 = s2u(Bs) + ((ncol + (l & 7)) * ASTR + (l >> 3) * 8) * 2;
    const uint32_t bbase2 = s2u(Bs) + ((ncol + (l & 7)) * ASTR + ((l >> 3) & 1) * 8 + 192) * 2;

    #pragma unroll 1
    for (int it = 0; it < ntile; it++) {
        const int cur = it & 1;
        uint32_t* Ac = cur ? As1 : As0;

        if (it + 1 < ntile) {
            int gtn = bid + (it + 1) * NCTA;
            stage_tile(cur ? As0 : As1, vq + (1 - cur) * NP,
                       enc, Va, bua, gtn >> 4, (gtn & 15) << 7, tid);
        }

        uint32_t a[13][4];
        {
            uint32_t abase = s2u(Ac) + ((mw * 16 + (l & 15)) * ASTR + (l >> 4) * 8) * 2;
            #pragma unroll
            for (int kt = 0; kt < 13; kt++)
                asm volatile("ldmatrix.sync.aligned.m8n8.x4.shared.b16 {%0,%1,%2,%3}, [%4];"
                    : "=r"(a[kt][0]), "=r"(a[kt][1]), "=r"(a[kt][2]), "=r"(a[kt][3])
                    : "r"(abase + kt * 32));
        }

        float slo = 0.f, shi = 0.f;
        const float2* vql = vq + cur * NP;
        #pragma unroll 1
        for (int jt = 0; jt < njt; jt++) {
            const uint32_t bb = bbase4 + (uint32_t)(jt * 8 * ASTR * 2);
            uint32_t bf[2][4];     // ring: 2 kt-pairs in flight
            uint32_t e0, e1;       // kt=12 tail
            #pragma unroll
            for (int p = 0; p < 2; p++)
                asm volatile("ldmatrix.sync.aligned.m8n8.x4.shared.b16 {%0,%1,%2,%3}, [%4];"
                    : "=r"(bf[p][0]), "=r"(bf[p][1]), "=r"(bf[p][2]), "=r"(bf[p][3])
                    : "r"(bb + p * 64));
            asm volatile("ldmatrix.sync.aligned.m8n8.x2.shared.b16 {%0,%1}, [%2];"
                : "=r"(e0), "=r"(e1) : "r"(bbase2 + (uint32_t)(jt * 8 * ASTR * 2)));

            // 3 accumulator chains: kt % 3  (depths 5/4/4)
            float c0 = 0.f, c1 = 0.f, c2 = 0.f, c3 = 0.f;
            float d0 = 0.f, d1 = 0.f, d2 = 0.f, d3 = 0.f;
            float g0 = 0.f, g1 = 0.f, g2 = 0.f, g3 = 0.f;
            #pragma unroll
            for (int p = 0; p < 6; p++) {
                const int slot = p & 1;
                uint32_t r0 = bf[slot][0], r1 = bf[slot][1];
                uint32_t r2 = bf[slot][2], r3 = bf[slot][3];
                if (p < 4)   // prefetch pair p+2
                    asm volatile("ldmatrix.sync.aligned.m8n8.x4.shared.b16 {%0,%1,%2,%3}, [%4];"
                        : "=r"(bf[slot][0]), "=r"(bf[slot][1]),
                          "=r"(bf[slot][2]), "=r"(bf[slot][3])
                        : "r"(bb + (p + 2) * 64));
                const int k0 = 2 * p, k1 = 2 * p + 1;
                // kt = k0 -> chain k0%3 ; kt = k1 -> chain k1%3
                if ((k0 % 3) == 0) {
                    asm volatile("mma.sync.aligned.m16n8k16.row.col.f32.bf16.bf16.f32 "
                        "{%0,%1,%2,%3},{%4,%5,%6,%7},{%8,%9},{%0,%1,%2,%3};"
                        : "+f"(c0), "+f"(c1), "+f"(c2), "+f"(c3)
                        : "r"(a[k0][0]), "r"(a[k0][1]), "r"(a[k0][2]), "r"(a[k0][3]),
                          "r"(r0), "r"(r1));
                } else if ((k0 % 3) == 1) {
                    asm volatile("mma.sync.aligned.m16n8k16.row.col.f32.bf16.bf16.f32 "
                        "{%0,%1,%2,%3},{%4,%5,%6,%7},{%8,%9},{%0,%1,%2,%3};"
                        : "+f"(d0), "+f"(d1), "+f"(d2), "+f"(d3)
                        : "r"(a[k0][0]), "r"(a[k0][1]), "r"(a[k0][2]), "r"(a[k0][3]),
                          "r"(r0), "r"(r1));
                } else {
                    asm volatile("mma.sync.aligned.m16n8k16.row.col.f32.bf16.bf16.f32 "
                        "{%0,%1,%2,%3},{%4,%5,%6,%7},{%8,%9},{%0,%1,%2,%3};"
                        : "+f"(g0), "+f"(g1), "+f"(g2), "+f"(g3)
                        : "r"(a[k0][0]), "r"(a[k0][1]), "r"(a[k0][2]), "r"(a[k0][3]),
                          "r"(r0), "r"(r1));
                }
                if ((k1 % 3) == 0) {
                    asm volatile("mma.sync.aligned.m16n8k16.row.col.f32.bf16.bf16.f32 "
                        "{%0,%1,%2,%3},{%4,%5,%6,%7},{%8,%9},{%0,%1,%2,%3};"
                        : "+f"(c0), "+f"(c1), "+f"(c2), "+f"(c3)
                        : "r"(a[k1][0]), "r"(a[k1][1]), "r"(a[k1][2]), "r"(a[k1][3]),
                          "r"(r2), "r"(r3));
                } else if ((k1 % 3) == 1) {
                    asm volatile("mma.sync.aligned.m16n8k16.row.col.f32.bf16.bf16.f32 "
                        "{%0,%1,%2,%3},{%4,%5,%6,%7},{%8,%9},{%0,%1,%2,%3};"
                        : "+f"(d0), "+f"(d1), "+f"(d2), "+f"(d3)
                        : "r"(a[k1][0]), "r"(a[k1][1]), "r"(a[k1][2]), "r"(a[k1][3]),
                          "r"(r2), "r"(r3));
                } else {
                    asm volatile("mma.sync.aligned.m16n8k16.row.col.f32.bf16.bf16.f32 "
                        "{%0,%1,%2,%3},{%4,%5,%6,%7},{%8,%9},{%0,%1,%2,%3};"
                        : "+f"(g0), "+f"(g1), "+f"(g2), "+f"(g3)
                        : "r"(a[k1][0]), "r"(a[k1][1]), "r"(a[k1][2]), "r"(a[k1][3]),
                          "r"(r2), "r"(r3));
                }
            }
            // kt = 12 -> 12 % 3 == 0 -> chain c
            asm volatile("mma.sync.aligned.m16n8k16.row.col.f32.bf16.bf16.f32 "
                "{%0,%1,%2,%3},{%4,%5,%6,%7},{%8,%9},{%0,%1,%2,%3};"
                : "+f"(c0), "+f"(c1), "+f"(c2), "+f"(c3)
                : "r"(a[12][0]), "r"(a[12][1]), "r"(a[12][2]), "r"(a[12][3]),
                  "r"(e0), "r"(e1));

            c0 += d0 + g0; c1 += d1 + g1; c2 += d2 + g2; c3 += d3 + g3;
            const int j0 = ncol + jt * 8 + 2 * (l & 3);
            const float2 v0 = vql[j0], v1 = vql[j0 + 1];
            slo = fmaf(v0.x, tanh_mufu(c0 + v0.y), slo);
            slo = fmaf(v1.x, tanh_mufu(c1 + v1.y), slo);
            shi = fmaf(v0.x, tanh_mufu(c2 + v0.y), shi);
            shi = fmaf(v1.x, tanh_mufu(c3 + v1.y), shi);
        }
        slo += __shfl_xor_sync(0xffffffffu, slo, 1);
        slo += __shfl_xor_sync(0xffffffffu, slo, 2);
        shi += __shfl_xor_sync(0xffffffffu, shi, 1);
        shi += __shfl_xor_sync(0xffffffffu, shi, 2);
        if ((l & 3) == 0) {
            srow[nw * 128 + mw * 16 + (l >> 2)] = slo;
            srow[nw * 128 + mw * 16 + (l >> 2) + 8] = shi;
        }
        __syncthreads();

        const int gt = bid + it * NCTA;
        if (tid < 128) {
            float s = srow[tid] + srow[128 + tid] + bv0;
            pbuf[tid] = exp2f(s * 1.4426950408889634f);
        }
        __syncthreads();
        if (wid == 0) {
            float dn = pbuf[l] + pbuf[l + 32] + pbuf[l + 64] + pbuf[l + 96];
            dn = warp_sum(dn);
            if (l == 0) g_denpart[gt] = dn;
        }
        {
            const int h2 = tid & 127, grp = tid >> 7;
            if (h2 < 100) {
                float ax = 0.f, ay = 0.f;
                #pragma unroll
                for (int i = 0; i < 32; i++) {
                    const int t = grp * 32 + i;
                    float pw = pbuf[t];
                    uint32_t u = Ac[t * AW + h2];
                    ax = fmaf(pw, __uint_as_float(u << 16), ax);
                    ay = fmaf(pw, __uint_as_float(u & 0xffff0000u), ay);
                }
                cpart[grp * NH + 2 * h2]     = ax;
                cpart[grp * NH + 2 * h2 + 1] = ay;
            }
        }
        __syncthreads();
        if (tid < NH)
            g_ctxpart[(size_t)gt * NH + tid] =
                cpart[tid] + cpart[NH + tid] + cpart[2 * NH + tid] + cpart[3 * NH + tid];
        __syncthreads();
    }
}

// ============================================================================
// K3: reduce ctx partials + gates + 5-step decode.  grid NB, 1024 thr.
// ============================================================================
#define SMEM_DEC ((20000 + 5000 + 64 + 128 + 64 + NH4 + NH4 + NH + NH + NH + 128 + 64 + 16 \
                   + 32 + 4 * NH) * 4)
__global__ __launch_bounds__(1024) void k_softdec(
    const float* __restrict__ x_in, const float* __restrict__ c0,
    const float* __restrict__ Wih, const float* __restrict__ bih,
    const float* __restrict__ W1, const float* __restrict__ b1,
    const float* __restrict__ W2, const float* __restrict__ b2,
    const float* __restrict__ W3, const float* __restrict__ b3,
    float* __restrict__ out) {
    extern __shared__ float sd[];
    float* W1s  = sd;
    float* W2s  = W1s + 20000;
    float* W3s  = W2s + 5000;
    float* b1s  = W3s + 64;
    float* b2s  = b1s + 128;
    float* gc   = b2s + 64;
    float* w0   = gc + NH4;
    float* ctxs = w0 + NH4;
    float* c0s  = ctxs + NH;
    float* buf0 = c0s + NH;
    float* buf1 = buf0 + NH;
    float* buf2 = buf1 + 128;
    float* xcur = buf2 + 64;
    float* red  = xcur + 16;
    float* part = red + 32;

    const int b = blockIdx.x, tid = threadIdx.x;
    const int w = tid >> 5, l = tid & 31;

    {
        const float4* W1v = (const float4*)W1;
        float4* W1sv = (float4*)W1s;
        #pragma unroll
        for (int i = tid; i < 5000; i += 1024) W1sv[i] = W1v[i];
        const float4* W2v = (const float4*)W2;
        float4* W2sv = (float4*)W2s;
        #pragma unroll
        for (int i = tid; i < 1250; i += 1024) W2sv[i] = W2v[i];
    }
    if (tid < 50) { W3s[tid] = W3[tid]; b2s[tid] = b2[tid]; }
    if (tid < 100) b1s[tid] = b1[tid];
    if (tid < NH) c0s[tid] = c0[b * NH + tid];
    if (tid == 0) xcur[0] = x_in[b];
    #pragma unroll
    for (int i = tid; i < NH4; i += 1024) w0[i] = Wih[(size_t)i * (NH + 1)];

    if (tid < 32) {
        float v = (tid < 16) ? g_denpart[b * 16 + tid] : 0.f;
        v = warp_sum(v);
        if (tid == 0) red[0] = 1.f / v;
    }
    {
        const int p = tid >> 8, hh = tid & 255;
        if (hh < NH) {
            const float* cp = g_ctxpart + ((size_t)b * 16 + p * 4) * NH + hh;
            float a = 0.f;
            #pragma unroll
            for (int i = 0; i < 4; i++) a += cp[(size_t)i * NH];
            part[p * NH + hh] = a;
        }
    }
    __syncthreads();
    const float inv = red[0];
    if (tid < NH)
        ctxs[tid] = (part[tid] + part[NH + tid] + part[2 * NH + tid] + part[3 * NH + tid]) * inv;
    __syncthreads();

    #pragma unroll 1
    for (int i = 0; i < 13; i++) {
        const int j0 = w * 25 + 2 * i;
        const bool has1 = (2 * i + 1 < 25);
        const int j1 = has1 ? j0 + 1 : j0;
        const float* r0 = Wih + (size_t)j0 * (NH + 1) + 1;
        const float* r1 = Wih + (size_t)j1 * (NH + 1) + 1;
        float s0 = 0.f, s1 = 0.f;
        #pragma unroll
        for (int k = l; k < NH; k += 32) {
            float c = ctxs[k];
            s0 = fmaf(c, r0[k], s0);
            s1 = fmaf(c, r1[k], s1);
        }
        s0 = warp_sum(s0);
        s1 = warp_sum(s1);
        if (l == 0) {
            gc[j0] = s0 + bih[j0] + g_hpre[b * NH4 + j0];
            if (has1) gc[j1] = s1 + bih[j1] + g_hpre[b * NH4 + j1];
        }
    }
    __syncthreads();

    const float b3v = b3[0];
    for (int st = 0; st < NSTEP; st++) {
        const float xv = xcur[0];
        if (tid < NH) {
            float gi = fmaf(xv, w0[tid], gc[tid]);
            float gf = fmaf(xv, w0[NH + tid], gc[NH + tid]);
            float gg = fmaf(xv, w0[2 * NH + tid], gc[2 * NH + tid]);
            float go = fmaf(xv, w0[3 * NH + tid], gc[3 * NH + tid]);
            float c  = sigm(gf) * c0s[tid] + sigm(gi) * tanhf(gg);
            buf0[tid] = fmaxf(sigm(go) * tanhf(c), 0.f);
        }
        __syncthreads();
        #pragma unroll
        for (int i = 0; i < 4; i++) {
            int j = w + 32 * i; int jj = min(j, 99);
            float s = 0.f;
            #pragma unroll
            for (int k = l; k < NH; k += 32) s = fmaf(W1s[jj * NH + k], buf0[k], s);
            s = warp_sum(s);
            if (l == 0 && j < 100) buf1[j] = fmaxf(s + b1s[j], 0.f);
        }
        __syncthreads();
        #pragma unroll
        for (int i = 0; i < 2; i++) {
            int j = w + 32 * i; int jj = min(j, 49);
            float s = 0.f;
            #pragma unroll
            for (int k = l; k < 100; k += 32) s = fmaf(W2s[jj * 100 + k], buf1[k], s);
            s = warp_sum(s);
            if (l == 0 && j < 50) buf2[j] = fmaxf(s + b2s[j], 0.f);
        }
        __syncthreads();
        if (w == 0) {
            float s = (l < 50) ? W3s[l] * buf2[l] : 0.f;
            if (l < 18) s = fmaf(W3s[l + 32], buf2[l + 32], s);
            s = warp_sum(s);
            if (l == 0) {
                float y = s + b3v;
                out[b * NSTEP + st] = y;
                xcur[0] = y;
            }
        }
        __syncthreads();
    }
}

// ============================================================================
extern "C" void kernel_launch(void* const* d_in, const int* in_sizes, int n_in,
                              void* d_out, int out_size) {
    const float* x   = (const float*)d_in[0];
    const float* h0  = (const float*)d_in[1];
    const float* c0  = (const float*)d_in[2];
    const float* enc = (const float*)d_in[3];
    const float* Wa  = (const float*)d_in[4];
    const float* ba  = (const float*)d_in[5];
    const float* Ua  = (const float*)d_in[6];
    const float* bua = (const float*)d_in[7];
    const float* Va  = (const float*)d_in[8];
    const float* bva = (const float*)d_in[9];
    const float* Wih = (const float*)d_in[10];
    const float* Whh = (const float*)d_in[11];
    const float* bih = (const float*)d_in[12];
    const float* bhh = (const float*)d_in[13];
    const float* W1  = (const float*)d_in[14];
    const float* b1  = (const float*)d_in[15];
    const float* W2  = (const float*)d_in[16];
    const float* b2  = (const float*)d_in[17];
    const float* W3  = (const float*)d_in[18];
    const float* b3  = (const float*)d_in[19];
    float* out = (float*)d_out;

    cudaFuncSetAttribute(k_scores, cudaFuncAttributeMaxDynamicSharedMemorySize,
                         (int)SMEM_SC);
    cudaFuncSetAttribute(k_softdec, cudaFuncAttributeMaxDynamicSharedMemorySize,
                         (int)SMEM_DEC);

    k_pre<<<dim3(40, 8), 256>>>(h0, Wa, ba, Whh, bhh);
    k_scores<<<NCTA, 512, SMEM_SC>>>(enc, Ua, bua, Va, bva);   // launch idx 5 (call 2) -> profiled
    k_softdec<<<NB, 1024, SMEM_DEC>>>(x, c0, Wih, bih,
                                      W1, b1, W2, b2, W3, b3, out);
    k_nop<<<1, 32>>>();
}

// round 16
// speedup vs baseline: 1.0219x; 1.0219x over previous
#include <cuda_runtime.h>
#include <cuda_bf16.h>
#include <math.h>
#include <stdint.h>

#define NB 128
#define NT 2048
#define NH 200
#define NH4 800
#define NSTEP 5

// ---- scratch ----
__device__ float g_qproj[NB * NH];
__device__ float g_hpre[NB * NH4];
__device__ float g_ctxpart[NB * 16 * NH];   // per-tile ctx partials
__device__ float g_denpart[NB * 16];        // per-tile denom partials

__device__ __forceinline__ float sigm(float x) { return 1.f / (1.f + expf(-x)); }

__device__ __forceinline__ float tanh_mufu(float x) {
    float m = x * 2.8853900817779268f;   // 2*log2(e)
    float e; asm("ex2.approx.ftz.f32 %0, %1;" : "=f"(e) : "f"(m));
    float d = 1.f + e;
    float rc; asm("rcp.approx.ftz.f32 %0, %1;" : "=f"(rc) : "f"(d));
    return fmaf(-2.f, rc, 1.f);
}

__device__ __forceinline__ uint32_t pack_bf2(float lo, float hi) {
    uint32_t r;
    asm("cvt.rn.bf16x2.f32 %0, %1, %2;" : "=r"(r) : "f"(hi), "f"(lo));
    return r;
}
__device__ __forceinline__ float warp_sum(float s) {
    #pragma unroll
    for (int o = 16; o; o >>= 1) s += __shfl_xor_sync(0xffffffffu, s, o);
    return s;
}
__device__ __forceinline__ uint32_t s2u(const void* p) {
    return (uint32_t)__cvta_generic_to_shared(p);
}

// ============================================================================
// K1: q_proj / h_pre gemv, weight-reuse tiling: grid(40, 8), 256 threads.
// ============================================================================
__global__ __launch_bounds__(256) void k_pre(
    const float* __restrict__ h0, const float* __restrict__ Wa,
    const float* __restrict__ ba, const float* __restrict__ Whh,
    const float* __restrict__ bhh) {
    const int oc = blockIdx.x, bg = blockIdx.y, tid = threadIdx.x;
    const int w = tid >> 5, l = tid & 31;
    __shared__ float hs[16 * NH];
    for (int i = tid; i < 16 * NH; i += 256)
        hs[i] = h0[(bg * 16 + i / NH) * NH + (i % NH)];
    __syncthreads();
    #pragma unroll 1
    for (int ol = 0; ol < 25; ol++) {
        const int o = oc * 25 + ol;
        const float* row = (o < NH) ? (Wa + o * NH) : (Whh + (o - NH) * NH);
        #pragma unroll
        for (int rep = 0; rep < 2; rep++) {
            const int bl = w * 2 + rep;
            const float* h = hs + bl * NH;
            float s = 0.f;
            #pragma unroll
            for (int k = l; k < NH; k += 32) s = fmaf(h[k], row[k], s);
            s = warp_sum(s);
            if (l == 0) {
                const int b = bg * 16 + bl;
                if (o < NH) g_qproj[b * NH + o] = s + ba[o];
                else        g_hpre[b * NH4 + (o - NH)] = s + bhh[o - NH];
            }
        }
    }
}

// ============================================================================
// K2: scores GEMM + fused softmax/ctx partials.  (R14 exact: best measured)
//   MT=128, 512 threads, 8 m-warps x 2 n-warps, 2-chain acc, 3-deep B ring.
// ============================================================================
#define NCTA 148
#define MT 128
#define NP 224
#define ASTR 216
#define AW 108
#define BS_U32 (NP * AW)
#define AS_U32 (MT * AW)
#define NTILES (NB * 16)
#define SMEM_SC ((BS_U32 + 2 * AS_U32) * 4 + 2 * NP * 8 + 256 * 4 + 128 * 4 + 4 * NH * 4 + 64)

__device__ __forceinline__ void stage_tile(
    uint32_t* __restrict__ dst, float2* __restrict__ vqd,
    const float* __restrict__ enc, const float* __restrict__ Va,
    const float* __restrict__ bua, int b, int trow, int tid) {
    const float* eb = enc + ((size_t)b * NT + trow) * NH;
    #pragma unroll
    for (int half = 0; half < 2; half++) {
        const int nb = half ? 13 : 14;
        const int base = half * 14;
        float2 f[14];
        #pragma unroll
        for (int i = 0; i < 14; i++) {
            if (i < nb) {
                int idx = tid + ((base + i) << 9);
                int r = idx / AW, p = idx - r * AW;
                f[i] = make_float2(0.f, 0.f);
                if (p < 100) f[i] = *(const float2*)(eb + r * NH + 2 * p);
            }
        }
        #pragma unroll
        for (int i = 0; i < 14; i++) {
            if (i < nb) {
                int idx = tid + ((base + i) << 9);
                dst[idx] = pack_bf2(f[i].x, f[i].y);
            }
        }
    }
    if (tid < NP) {
        float vv = 0.f, qq = 0.f;
        if (tid < NH) { vv = Va[tid]; qq = g_qproj[b * NH + tid] + bua[tid]; }
        vqd[tid] = make_float2(vv, qq);
    }
}

__global__ __launch_bounds__(512, 1) void k_scores(
    const float* __restrict__ enc, const float* __restrict__ Ua,
    const float* __restrict__ bua, const float* __restrict__ Va,
    const float* __restrict__ bva) {
    extern __shared__ uint32_t sm32[];
    uint32_t* Bs  = sm32;
    uint32_t* As0 = Bs + BS_U32;
    uint32_t* As1 = As0 + AS_U32;
    float2*   vq  = (float2*)(As1 + AS_U32);
    float*    srow = (float*)(vq + 2 * NP);     // [2][128]
    float*    pbuf = srow + 256;                // [128]
    float*    cpart = pbuf + 128;               // [4][200]

    const int tid = threadIdx.x, l = tid & 31, wid = tid >> 5;
    const int mw = wid & 7, nw = wid >> 3;      // 8 m-warps x 2 n-warps
    const int bid = blockIdx.x;
    const float bv0 = bva[0];
    const int njt = (nw == 0) ? 13 : 12;
    const int ncol = nw ? 104 : 0;

    for (int i = tid; i < BS_U32; i += 512) Bs[i] = 0;
    __syncthreads();
    for (int i = tid; i < NH * 100; i += 512) {
        int n = i / 100, k2 = i - n * 100;
        float2 f = *(const float2*)(Ua + n * NH + 2 * k2);
        Bs[n * AW + k2] = pack_bf2(f.x, f.y);
    }

    const int ntile = (NTILES - bid + NCTA - 1) / NCTA;
    {
        int gt = bid;
        stage_tile(As0, vq, enc, Va, bua, gt >> 4, (gt & 15) << 7, tid);
    }
    __syncthreads();

    const uint32_t bbase4 = s2u(Bs) + ((ncol + (l & 7)) * ASTR + (l >> 3) * 8) * 2;
    const uint32_t bbase2 = s2u(Bs) + ((ncol + (l & 7)) * ASTR + ((l >> 3) & 1) * 8 + 192) * 2;

    #pragma unroll 1
    for (int it = 0; it < ntile; it++) {
        const int cur = it & 1;
        uint32_t* Ac = cur ? As1 : As0;

        if (it + 1 < ntile) {
            int gtn = bid + (it + 1) * NCTA;
            stage_tile(cur ? As0 : As1, vq + (1 - cur) * NP,
                       enc, Va, bua, gtn >> 4, (gtn & 15) << 7, tid);
        }

        uint32_t a[13][4];
        {
            uint32_t abase = s2u(Ac) + ((mw * 16 + (l & 15)) * ASTR + (l >> 4) * 8) * 2;
            #pragma unroll
            for (int kt = 0; kt < 13; kt++)
                asm volatile("ldmatrix.sync.aligned.m8n8.x4.shared.b16 {%0,%1,%2,%3}, [%4];"
                    : "=r"(a[kt][0]), "=r"(a[kt][1]), "=r"(a[kt][2]), "=r"(a[kt][3])
                    : "r"(abase + kt * 32));
        }

        float slo = 0.f, shi = 0.f;
        const float2* vql = vq + cur * NP;
        #pragma unroll 1
        for (int jt = 0; jt < njt; jt++) {
            const uint32_t bb = bbase4 + (uint32_t)(jt * 8 * ASTR * 2);
            uint32_t bf[3][4];
            uint32_t e0, e1;
            #pragma unroll
            for (int p = 0; p < 3; p++)
                asm volatile("ldmatrix.sync.aligned.m8n8.x4.shared.b16 {%0,%1,%2,%3}, [%4];"
                    : "=r"(bf[p][0]), "=r"(bf[p][1]), "=r"(bf[p][2]), "=r"(bf[p][3])
                    : "r"(bb + p * 64));
            asm volatile("ldmatrix.sync.aligned.m8n8.x2.shared.b16 {%0,%1}, [%2];"
                : "=r"(e0), "=r"(e1) : "r"(bbase2 + (uint32_t)(jt * 8 * ASTR * 2)));

            float c0 = 0.f, c1 = 0.f, c2 = 0.f, c3 = 0.f;
            float d0 = 0.f, d1 = 0.f, d2 = 0.f, d3 = 0.f;
            #pragma unroll
            for (int p = 0; p < 6; p++) {
                const int slot = p % 3;
                uint32_t r0 = bf[slot][0], r1 = bf[slot][1];
                uint32_t r2 = bf[slot][2], r3 = bf[slot][3];
                if (p < 3)
                    asm volatile("ldmatrix.sync.aligned.m8n8.x4.shared.b16 {%0,%1,%2,%3}, [%4];"
                        : "=r"(bf[slot][0]), "=r"(bf[slot][1]),
                          "=r"(bf[slot][2]), "=r"(bf[slot][3])
                        : "r"(bb + (p + 3) * 64));
                asm volatile("mma.sync.aligned.m16n8k16.row.col.f32.bf16.bf16.f32 "
                    "{%0,%1,%2,%3},{%4,%5,%6,%7},{%8,%9},{%0,%1,%2,%3};"
                    : "+f"(c0), "+f"(c1), "+f"(c2), "+f"(c3)
                    : "r"(a[2*p][0]), "r"(a[2*p][1]), "r"(a[2*p][2]), "r"(a[2*p][3]),
                      "r"(r0), "r"(r1));
                asm volatile("mma.sync.aligned.m16n8k16.row.col.f32.bf16.bf16.f32 "
                    "{%0,%1,%2,%3},{%4,%5,%6,%7},{%8,%9},{%0,%1,%2,%3};"
                    : "+f"(d0), "+f"(d1), "+f"(d2), "+f"(d3)
                    : "r"(a[2*p+1][0]), "r"(a[2*p+1][1]), "r"(a[2*p+1][2]), "r"(a[2*p+1][3]),
                      "r"(r2), "r"(r3));
            }
            asm volatile("mma.sync.aligned.m16n8k16.row.col.f32.bf16.bf16.f32 "
                "{%0,%1,%2,%3},{%4,%5,%6,%7},{%8,%9},{%0,%1,%2,%3};"
                : "+f"(c0), "+f"(c1), "+f"(c2), "+f"(c3)
                : "r"(a[12][0]), "r"(a[12][1]), "r"(a[12][2]), "r"(a[12][3]),
                  "r"(e0), "r"(e1));

            c0 += d0; c1 += d1; c2 += d2; c3 += d3;
            const int j0 = ncol + jt * 8 + 2 * (l & 3);
            const float2 v0 = vql[j0], v1 = vql[j0 + 1];
            slo = fmaf(v0.x, tanh_mufu(c0 + v0.y), slo);
            slo = fmaf(v1.x, tanh_mufu(c1 + v1.y), slo);
            shi = fmaf(v0.x, tanh_mufu(c2 + v0.y), shi);
            shi = fmaf(v1.x, tanh_mufu(c3 + v1.y), shi);
        }
        slo += __shfl_xor_sync(0xffffffffu, slo, 1);
        slo += __shfl_xor_sync(0xffffffffu, slo, 2);
        shi += __shfl_xor_sync(0xffffffffu, shi, 1);
        shi += __shfl_xor_sync(0xffffffffu, shi, 2);
        if ((l & 3) == 0) {
            srow[nw * 128 + mw * 16 + (l >> 2)] = slo;
            srow[nw * 128 + mw * 16 + (l >> 2) + 8] = shi;
        }
        __syncthreads();

        const int gt = bid + it * NCTA;
        if (tid < 128) {
            float s = srow[tid] + srow[128 + tid] + bv0;
            pbuf[tid] = exp2f(s * 1.4426950408889634f);
        }
        __syncthreads();
        if (wid == 0) {
            float dn = pbuf[l] + pbuf[l + 32] + pbuf[l + 64] + pbuf[l + 96];
            dn = warp_sum(dn);
            if (l == 0) g_denpart[gt] = dn;
        }
        {
            const int h2 = tid & 127, grp = tid >> 7;
            if (h2 < 100) {
                float ax = 0.f, ay = 0.f;
                #pragma unroll
                for (int i = 0; i < 32; i++) {
                    const int t = grp * 32 + i;
                    float pw = pbuf[t];
                    uint32_t u = Ac[t * AW + h2];
                    ax = fmaf(pw, __uint_as_float(u << 16), ax);
                    ay = fmaf(pw, __uint_as_float(u & 0xffff0000u), ay);
                }
                cpart[grp * NH + 2 * h2]     = ax;
                cpart[grp * NH + 2 * h2 + 1] = ay;
            }
        }
        __syncthreads();
        if (tid < NH)
            g_ctxpart[(size_t)gt * NH + tid] =
                cpart[tid] + cpart[NH + tid] + cpart[2 * NH + tid] + cpart[3 * NH + tid];
        __syncthreads();
    }
}

// ============================================================================
// K3: reduce ctx partials + gates + 5-step decode.  grid NB, 1024 thr.
// ============================================================================
#define SMEM_DEC ((20000 + 5000 + 64 + 128 + 64 + NH4 + NH4 + NH + NH + NH + 128 + 64 + 16 \
                   + 32 + 4 * NH) * 4)
__global__ __launch_bounds__(1024) void k_softdec(
    const float* __restrict__ x_in, const float* __restrict__ c0,
    const float* __restrict__ Wih, const float* __restrict__ bih,
    const float* __restrict__ W1, const float* __restrict__ b1,
    const float* __restrict__ W2, const float* __restrict__ b2,
    const float* __restrict__ W3, const float* __restrict__ b3,
    float* __restrict__ out) {
    extern __shared__ float sd[];
    float* W1s  = sd;
    float* W2s  = W1s + 20000;
    float* W3s  = W2s + 5000;
    float* b1s  = W3s + 64;
    float* b2s  = b1s + 128;
    float* gc   = b2s + 64;
    float* w0   = gc + NH4;
    float* ctxs = w0 + NH4;
    float* c0s  = ctxs + NH;
    float* buf0 = c0s + NH;
    float* buf1 = buf0 + NH;
    float* buf2 = buf1 + 128;
    float* xcur = buf2 + 64;
    float* red  = xcur + 16;
    float* part = red + 32;

    const int b = blockIdx.x, tid = threadIdx.x;
    const int w = tid >> 5, l = tid & 31;

    {
        const float4* W1v = (const float4*)W1;
        float4* W1sv = (float4*)W1s;
        #pragma unroll
        for (int i = tid; i < 5000; i += 1024) W1sv[i] = W1v[i];
        const float4* W2v = (const float4*)W2;
        float4* W2sv = (float4*)W2s;
        #pragma unroll
        for (int i = tid; i < 1250; i += 1024) W2sv[i] = W2v[i];
    }
    if (tid < 50) { W3s[tid] = W3[tid]; b2s[tid] = b2[tid]; }
    if (tid < 100) b1s[tid] = b1[tid];
    if (tid < NH) c0s[tid] = c0[b * NH + tid];
    if (tid == 0) xcur[0] = x_in[b];
    #pragma unroll
    for (int i = tid; i < NH4; i += 1024) w0[i] = Wih[(size_t)i * (NH + 1)];

    if (tid < 32) {
        float v = (tid < 16) ? g_denpart[b * 16 + tid] : 0.f;
        v = warp_sum(v);
        if (tid == 0) red[0] = 1.f / v;
    }
    {
        const int p = tid >> 8, hh = tid & 255;
        if (hh < NH) {
            const float* cp = g_ctxpart + ((size_t)b * 16 + p * 4) * NH + hh;
            float a = 0.f;
            #pragma unroll
            for (int i = 0; i < 4; i++) a += cp[(size_t)i * NH];
            part[p * NH + hh] = a;
        }
    }
    __syncthreads();
    const float inv = red[0];
    if (tid < NH)
        ctxs[tid] = (part[tid] + part[NH + tid] + part[2 * NH + tid] + part[3 * NH + tid]) * inv;
    __syncthreads();

    #pragma unroll 1
    for (int i = 0; i < 13; i++) {
        const int j0 = w * 25 + 2 * i;
        const bool has1 = (2 * i + 1 < 25);
        const int j1 = has1 ? j0 + 1 : j0;
        const float* r0 = Wih + (size_t)j0 * (NH + 1) + 1;
        const float* r1 = Wih + (size_t)j1 * (NH + 1) + 1;
        float s0 = 0.f, s1 = 0.f;
        #pragma unroll
        for (int k = l; k < NH; k += 32) {
            float c = ctxs[k];
            s0 = fmaf(c, r0[k], s0);
            s1 = fmaf(c, r1[k], s1);
        }
        s0 = warp_sum(s0);
        s1 = warp_sum(s1);
        if (l == 0) {
            gc[j0] = s0 + bih[j0] + g_hpre[b * NH4 + j0];
            if (has1) gc[j1] = s1 + bih[j1] + g_hpre[b * NH4 + j1];
        }
    }
    __syncthreads();

    const float b3v = b3[0];
    for (int st = 0; st < NSTEP; st++) {
        const float xv = xcur[0];
        if (tid < NH) {
            float gi = fmaf(xv, w0[tid], gc[tid]);
            float gf = fmaf(xv, w0[NH + tid], gc[NH + tid]);
            float gg = fmaf(xv, w0[2 * NH + tid], gc[2 * NH + tid]);
            float go = fmaf(xv, w0[3 * NH + tid], gc[3 * NH + tid]);
            float c  = sigm(gf) * c0s[tid] + sigm(gi) * tanhf(gg);
            buf0[tid] = fmaxf(sigm(go) * tanhf(c), 0.f);
        }
        __syncthreads();
        #pragma unroll
        for (int i = 0; i < 4; i++) {
            int j = w + 32 * i; int jj = min(j, 99);
            float s = 0.f;
            #pragma unroll
            for (int k = l; k < NH; k += 32) s = fmaf(W1s[jj * NH + k], buf0[k], s);
            s = warp_sum(s);
            if (l == 0 && j < 100) buf1[j] = fmaxf(s + b1s[j], 0.f);
        }
        __syncthreads();
        #pragma unroll
        for (int i = 0; i < 2; i++) {
            int j = w + 32 * i; int jj = min(j, 49);
            float s = 0.f;
            #pragma unroll
            for (int k = l; k < 100; k += 32) s = fmaf(W2s[jj * 100 + k], buf1[k], s);
            s = warp_sum(s);
            if (l == 0 && j < 50) buf2[j] = fmaxf(s + b2s[j], 0.f);
        }
        __syncthreads();
        if (w == 0) {
            float s = (l < 50) ? W3s[l] * buf2[l] : 0.f;
            if (l < 18) s = fmaf(W3s[l + 32], buf2[l + 32], s);
            s = warp_sum(s);
            if (l == 0) {
                float y = s + b3v;
                out[b * NSTEP + st] = y;
                xcur[0] = y;
            }
        }
        __syncthreads();
    }
}

// ============================================================================
extern "C" void kernel_launch(void* const* d_in, const int* in_sizes, int n_in,
                              void* d_out, int out_size) {
    const float* x   = (const float*)d_in[0];
    const float* h0  = (const float*)d_in[1];
    const float* c0  = (const float*)d_in[2];
    const float* enc = (const float*)d_in[3];
    const float* Wa  = (const float*)d_in[4];
    const float* ba  = (const float*)d_in[5];
    const float* Ua  = (const float*)d_in[6];
    const float* bua = (const float*)d_in[7];
    const float* Va  = (const float*)d_in[8];
    const float* bva = (const float*)d_in[9];
    const float* Wih = (const float*)d_in[10];
    const float* Whh = (const float*)d_in[11];
    const float* bih = (const float*)d_in[12];
    const float* bhh = (const float*)d_in[13];
    const float* W1  = (const float*)d_in[14];
    const float* b1  = (const float*)d_in[15];
    const float* W2  = (const float*)d_in[16];
    const float* b2  = (const float*)d_in[17];
    const float* W3  = (const float*)d_in[18];
    const float* b3  = (const float*)d_in[19];
    float* out = (float*)d_out;

    cudaFuncSetAttribute(k_scores, cudaFuncAttributeMaxDynamicSharedMemorySize,
                         (int)SMEM_SC);
    cudaFuncSetAttribute(k_softdec, cudaFuncAttributeMaxDynamicSharedMemorySize,
                         (int)SMEM_DEC);

    // 3 launches/call; ncu -s 5 -c 1 lands on call-2's k_softdec.
    k_pre<<<dim3(40, 8), 256>>>(h0, Wa, ba, Whh, bhh);
    k_scores<<<NCTA, 512, SMEM_SC>>>(enc, Ua, bua, Va, bva);
    k_softdec<<<NB, 1024, SMEM_DEC>>>(x, c0, Wih, bih,
                                      W1, b1, W2, b2, W3, b3, out);
}

// round 17
// speedup vs baseline: 1.0746x; 1.0515x over previous
#include <cuda_runtime.h>
#include <cuda_bf16.h>
#include <math.h>
#include <stdint.h>

#define NB 128
#define NT 2048
#define NH 200
#define NH4 800
#define NSTEP 5

// ---- scratch ----
__device__ float g_qproj[NB * NH];
__device__ float g_hpre[NB * NH4];
__device__ float g_ctxpart[NB * 16 * NH];   // per-tile ctx partials
__device__ float g_denpart[NB * 16];        // per-tile denom partials

__device__ __forceinline__ float sigm(float x) { return 1.f / (1.f + expf(-x)); }

__device__ __forceinline__ float tanh_mufu(float x) {
    float m = x * 2.8853900817779268f;   // 2*log2(e)
    float e; asm("ex2.approx.ftz.f32 %0, %1;" : "=f"(e) : "f"(m));
    float d = 1.f + e;
    float rc; asm("rcp.approx.ftz.f32 %0, %1;" : "=f"(rc) : "f"(d));
    return fmaf(-2.f, rc, 1.f);
}

__device__ __forceinline__ uint32_t pack_bf2(float lo, float hi) {
    uint32_t r;
    asm("cvt.rn.bf16x2.f32 %0, %1, %2;" : "=r"(r) : "f"(hi), "f"(lo));
    return r;
}
__device__ __forceinline__ float warp_sum(float s) {
    #pragma unroll
    for (int o = 16; o; o >>= 1) s += __shfl_xor_sync(0xffffffffu, s, o);
    return s;
}
__device__ __forceinline__ uint32_t s2u(const void* p) {
    return (uint32_t)__cvta_generic_to_shared(p);
}

// ============================================================================
// K1: q_proj/h_pre as a register-reuse gemv.  grid(125), 256 threads.
//   All of h0 (128x200) staged in smem padded to 201 (conflict-free lane=b).
//   Warp owns output row o; w[o][k] is an L1 broadcast; 4 accumulators per
//   lane (b = l, l+32, l+64, l+96) give 4 independent FMA chains + 4x reuse.
// ============================================================================
#define SMEM_PRE (NB * 201 * 4)
__global__ __launch_bounds__(256) void k_pre(
    const float* __restrict__ h0, const float* __restrict__ Wa,
    const float* __restrict__ ba, const float* __restrict__ Whh,
    const float* __restrict__ bhh) {
    extern __shared__ float hs[];    // [128][201]
    const int tid = threadIdx.x, w = tid >> 5, l = tid & 31;

    for (int i = tid; i < NB * 100; i += 256) {
        int b = i / 100, k2 = i - b * 100;
        float2 v = *(const float2*)(h0 + b * NH + 2 * k2);
        hs[b * 201 + 2 * k2] = v.x;
        hs[b * 201 + 2 * k2 + 1] = v.y;
    }
    __syncthreads();

    const int o = blockIdx.x * 8 + w;          // 0..999
    const float* row = (o < NH) ? (Wa + o * NH) : (Whh + (o - NH) * NH);
    const float bias = (o < NH) ? ba[o] : bhh[o - NH];

    float a0 = 0.f, a1 = 0.f, a2 = 0.f, a3 = 0.f;
    const float* h0p = hs + l * 201;
    const float* h1p = hs + (l + 32) * 201;
    const float* h2p = hs + (l + 64) * 201;
    const float* h3p = hs + (l + 96) * 201;
    #pragma unroll 8
    for (int k = 0; k < NH; k++) {
        float wv = __ldg(row + k);
        a0 = fmaf(wv, h0p[k], a0);
        a1 = fmaf(wv, h1p[k], a1);
        a2 = fmaf(wv, h2p[k], a2);
        a3 = fmaf(wv, h3p[k], a3);
    }
    float acc[4] = {a0, a1, a2, a3};
    #pragma unroll
    for (int p = 0; p < 4; p++) {
        const int b = p * 32 + l;
        if (o < NH) g_qproj[b * NH + o] = acc[p] + bias;
        else        g_hpre[b * NH4 + (o - NH)] = acc[p] + bias;
    }
}

// ============================================================================
// K2: scores GEMM + fused softmax/ctx partials.  (R14 exact: best measured)
//   MT=128, 512 threads, 8 m-warps x 2 n-warps, 2-chain acc, 3-deep B ring.
// ============================================================================
#define NCTA 148
#define MT 128
#define NP 224
#define ASTR 216
#define AW 108
#define BS_U32 (NP * AW)
#define AS_U32 (MT * AW)
#define NTILES (NB * 16)
#define SMEM_SC ((BS_U32 + 2 * AS_U32) * 4 + 2 * NP * 8 + 256 * 4 + 128 * 4 + 4 * NH * 4 + 64)

__device__ __forceinline__ void stage_tile(
    uint32_t* __restrict__ dst, float2* __restrict__ vqd,
    const float* __restrict__ enc, const float* __restrict__ Va,
    const float* __restrict__ bua, int b, int trow, int tid) {
    const float* eb = enc + ((size_t)b * NT + trow) * NH;
    #pragma unroll
    for (int half = 0; half < 2; half++) {
        const int nb = half ? 13 : 14;
        const int base = half * 14;
        float2 f[14];
        #pragma unroll
        for (int i = 0; i < 14; i++) {
            if (i < nb) {
                int idx = tid + ((base + i) << 9);
                int r = idx / AW, p = idx - r * AW;
                f[i] = make_float2(0.f, 0.f);
                if (p < 100) f[i] = *(const float2*)(eb + r * NH + 2 * p);
            }
        }
        #pragma unroll
        for (int i = 0; i < 14; i++) {
            if (i < nb) {
                int idx = tid + ((base + i) << 9);
                dst[idx] = pack_bf2(f[i].x, f[i].y);
            }
        }
    }
    if (tid < NP) {
        float vv = 0.f, qq = 0.f;
        if (tid < NH) { vv = Va[tid]; qq = g_qproj[b * NH + tid] + bua[tid]; }
        vqd[tid] = make_float2(vv, qq);
    }
}

__global__ __launch_bounds__(512, 1) void k_scores(
    const float* __restrict__ enc, const float* __restrict__ Ua,
    const float* __restrict__ bua, const float* __restrict__ Va,
    const float* __restrict__ bva) {
    extern __shared__ uint32_t sm32[];
    uint32_t* Bs  = sm32;
    uint32_t* As0 = Bs + BS_U32;
    uint32_t* As1 = As0 + AS_U32;
    float2*   vq  = (float2*)(As1 + AS_U32);
    float*    srow = (float*)(vq + 2 * NP);     // [2][128]
    float*    pbuf = srow + 256;                // [128]
    float*    cpart = pbuf + 128;               // [4][200]

    const int tid = threadIdx.x, l = tid & 31, wid = tid >> 5;
    const int mw = wid & 7, nw = wid >> 3;      // 8 m-warps x 2 n-warps
    const int bid = blockIdx.x;
    const float bv0 = bva[0];
    const int njt = (nw == 0) ? 13 : 12;
    const int ncol = nw ? 104 : 0;

    for (int i = tid; i < BS_U32; i += 512) Bs[i] = 0;
    __syncthreads();
    for (int i = tid; i < NH * 100; i += 512) {
        int n = i / 100, k2 = i - n * 100;
        float2 f = *(const float2*)(Ua + n * NH + 2 * k2);
        Bs[n * AW + k2] = pack_bf2(f.x, f.y);
    }

    const int ntile = (NTILES - bid + NCTA - 1) / NCTA;
    {
        int gt = bid;
        stage_tile(As0, vq, enc, Va, bua, gt >> 4, (gt & 15) << 7, tid);
    }
    __syncthreads();

    const uint32_t bbase4 = s2u(Bs) + ((ncol + (l & 7)) * ASTR + (l >> 3) * 8) * 2;
    const uint32_t bbase2 = s2u(Bs) + ((ncol + (l & 7)) * ASTR + ((l >> 3) & 1) * 8 + 192) * 2;

    #pragma unroll 1
    for (int it = 0; it < ntile; it++) {
        const int cur = it & 1;
        uint32_t* Ac = cur ? As1 : As0;

        if (it + 1 < ntile) {
            int gtn = bid + (it + 1) * NCTA;
            stage_tile(cur ? As0 : As1, vq + (1 - cur) * NP,
                       enc, Va, bua, gtn >> 4, (gtn & 15) << 7, tid);
        }

        uint32_t a[13][4];
        {
            uint32_t abase = s2u(Ac) + ((mw * 16 + (l & 15)) * ASTR + (l >> 4) * 8) * 2;
            #pragma unroll
            for (int kt = 0; kt < 13; kt++)
                asm volatile("ldmatrix.sync.aligned.m8n8.x4.shared.b16 {%0,%1,%2,%3}, [%4];"
                    : "=r"(a[kt][0]), "=r"(a[kt][1]), "=r"(a[kt][2]), "=r"(a[kt][3])
                    : "r"(abase + kt * 32));
        }

        float slo = 0.f, shi = 0.f;
        const float2* vql = vq + cur * NP;
        #pragma unroll 1
        for (int jt = 0; jt < njt; jt++) {
            const uint32_t bb = bbase4 + (uint32_t)(jt * 8 * ASTR * 2);
            uint32_t bf[3][4];
            uint32_t e0, e1;
            #pragma unroll
            for (int p = 0; p < 3; p++)
                asm volatile("ldmatrix.sync.aligned.m8n8.x4.shared.b16 {%0,%1,%2,%3}, [%4];"
                    : "=r"(bf[p][0]), "=r"(bf[p][1]), "=r"(bf[p][2]), "=r"(bf[p][3])
                    : "r"(bb + p * 64));
            asm volatile("ldmatrix.sync.aligned.m8n8.x2.shared.b16 {%0,%1}, [%2];"
                : "=r"(e0), "=r"(e1) : "r"(bbase2 + (uint32_t)(jt * 8 * ASTR * 2)));

            float c0 = 0.f, c1 = 0.f, c2 = 0.f, c3 = 0.f;
            float d0 = 0.f, d1 = 0.f, d2 = 0.f, d3 = 0.f;
            #pragma unroll
            for (int p = 0; p < 6; p++) {
                const int slot = p % 3;
                uint32_t r0 = bf[slot][0], r1 = bf[slot][1];
                uint32_t r2 = bf[slot][2], r3 = bf[slot][3];
                if (p < 3)
                    asm volatile("ldmatrix.sync.aligned.m8n8.x4.shared.b16 {%0,%1,%2,%3}, [%4];"
                        : "=r"(bf[slot][0]), "=r"(bf[slot][1]),
                          "=r"(bf[slot][2]), "=r"(bf[slot][3])
                        : "r"(bb + (p + 3) * 64));
                asm volatile("mma.sync.aligned.m16n8k16.row.col.f32.bf16.bf16.f32 "
                    "{%0,%1,%2,%3},{%4,%5,%6,%7},{%8,%9},{%0,%1,%2,%3};"
                    : "+f"(c0), "+f"(c1), "+f"(c2), "+f"(c3)
                    : "r"(a[2*p][0]), "r"(a[2*p][1]), "r"(a[2*p][2]), "r"(a[2*p][3]),
                      "r"(r0), "r"(r1));
                asm volatile("mma.sync.aligned.m16n8k16.row.col.f32.bf16.bf16.f32 "
                    "{%0,%1,%2,%3},{%4,%5,%6,%7},{%8,%9},{%0,%1,%2,%3};"
                    : "+f"(d0), "+f"(d1), "+f"(d2), "+f"(d3)
                    : "r"(a[2*p+1][0]), "r"(a[2*p+1][1]), "r"(a[2*p+1][2]), "r"(a[2*p+1][3]),
                      "r"(r2), "r"(r3));
            }
            asm volatile("mma.sync.aligned.m16n8k16.row.col.f32.bf16.bf16.f32 "
                "{%0,%1,%2,%3},{%4,%5,%6,%7},{%8,%9},{%0,%1,%2,%3};"
                : "+f"(c0), "+f"(c1), "+f"(c2), "+f"(c3)
                : "r"(a[12][0]), "r"(a[12][1]), "r"(a[12][2]), "r"(a[12][3]),
                  "r"(e0), "r"(e1));

            c0 += d0; c1 += d1; c2 += d2; c3 += d3;
            const int j0 = ncol + jt * 8 + 2 * (l & 3);
            const float2 v0 = vql[j0], v1 = vql[j0 + 1];
            slo = fmaf(v0.x, tanh_mufu(c0 + v0.y), slo);
            slo = fmaf(v1.x, tanh_mufu(c1 + v1.y), slo);
            shi = fmaf(v0.x, tanh_mufu(c2 + v0.y), shi);
            shi = fmaf(v1.x, tanh_mufu(c3 + v1.y), shi);
        }
        slo += __shfl_xor_sync(0xffffffffu, slo, 1);
        slo += __shfl_xor_sync(0xffffffffu, slo, 2);
        shi += __shfl_xor_sync(0xffffffffu, shi, 1);
        shi += __shfl_xor_sync(0xffffffffu, shi, 2);
        if ((l & 3) == 0) {
            srow[nw * 128 + mw * 16 + (l >> 2)] = slo;
            srow[nw * 128 + mw * 16 + (l >> 2) + 8] = shi;
        }
        __syncthreads();

        const int gt = bid + it * NCTA;
        if (tid < 128) {
            float s = srow[tid] + srow[128 + tid] + bv0;
            pbuf[tid] = exp2f(s * 1.4426950408889634f);
        }
        __syncthreads();
        if (wid == 0) {
            float dn = pbuf[l] + pbuf[l + 32] + pbuf[l + 64] + pbuf[l + 96];
            dn = warp_sum(dn);
            if (l == 0) g_denpart[gt] = dn;
        }
        {
            const int h2 = tid & 127, grp = tid >> 7;
            if (h2 < 100) {
                float ax = 0.f, ay = 0.f;
                #pragma unroll
                for (int i = 0; i < 32; i++) {
                    const int t = grp * 32 + i;
                    float pw = pbuf[t];
                    uint32_t u = Ac[t * AW + h2];
                    ax = fmaf(pw, __uint_as_float(u << 16), ax);
                    ay = fmaf(pw, __uint_as_float(u & 0xffff0000u), ay);
                }
                cpart[grp * NH + 2 * h2]     = ax;
                cpart[grp * NH + 2 * h2 + 1] = ay;
            }
        }
        __syncthreads();
        if (tid < NH)
            g_ctxpart[(size_t)gt * NH + tid] =
                cpart[tid] + cpart[NH + tid] + cpart[2 * NH + tid] + cpart[3 * NH + tid];
        __syncthreads();
    }
}

// ============================================================================
// K3: reduce ctx partials + gates + 5-step decode.  grid NB, 1024 thr.
// ============================================================================
#define SMEM_DEC ((20000 + 5000 + 64 + 128 + 64 + NH4 + NH4 + NH + NH + NH + 128 + 64 + 16 \
                   + 32 + 4 * NH) * 4)
__global__ __launch_bounds__(1024) void k_softdec(
    const float* __restrict__ x_in, const float* __restrict__ c0,
    const float* __restrict__ Wih, const float* __restrict__ bih,
    const float* __restrict__ W1, const float* __restrict__ b1,
    const float* __restrict__ W2, const float* __restrict__ b2,
    const float* __restrict__ W3, const float* __restrict__ b3,
    float* __restrict__ out) {
    extern __shared__ float sd[];
    float* W1s  = sd;
    float* W2s  = W1s + 20000;
    float* W3s  = W2s + 5000;
    float* b1s  = W3s + 64;
    float* b2s  = b1s + 128;
    float* gc   = b2s + 64;
    float* w0   = gc + NH4;
    float* ctxs = w0 + NH4;
    float* c0s  = ctxs + NH;
    float* buf0 = c0s + NH;
    float* buf1 = buf0 + NH;
    float* buf2 = buf1 + 128;
    float* xcur = buf2 + 64;
    float* red  = xcur + 16;
    float* part = red + 32;

    const int b = blockIdx.x, tid = threadIdx.x;
    const int w = tid >> 5, l = tid & 31;

    {
        const float4* W1v = (const float4*)W1;
        float4* W1sv = (float4*)W1s;
        #pragma unroll
        for (int i = tid; i < 5000; i += 1024) W1sv[i] = W1v[i];
        const float4* W2v = (const float4*)W2;
        float4* W2sv = (float4*)W2s;
        #pragma unroll
        for (int i = tid; i < 1250; i += 1024) W2sv[i] = W2v[i];
    }
    if (tid < 50) { W3s[tid] = W3[tid]; b2s[tid] = b2[tid]; }
    if (tid < 100) b1s[tid] = b1[tid];
    if (tid < NH) c0s[tid] = c0[b * NH + tid];
    if (tid == 0) xcur[0] = x_in[b];
    #pragma unroll
    for (int i = tid; i < NH4; i += 1024) w0[i] = Wih[(size_t)i * (NH + 1)];

    if (tid < 32) {
        float v = (tid < 16) ? g_denpart[b * 16 + tid] : 0.f;
        v = warp_sum(v);
        if (tid == 0) red[0] = 1.f / v;
    }
    {
        const int p = tid >> 8, hh = tid & 255;
        if (hh < NH) {
            const float* cp = g_ctxpart + ((size_t)b * 16 + p * 4) * NH + hh;
            float a = 0.f;
            #pragma unroll
            for (int i = 0; i < 4; i++) a += cp[(size_t)i * NH];
            part[p * NH + hh] = a;
        }
    }
    __syncthreads();
    const float inv = red[0];
    if (tid < NH)
        ctxs[tid] = (part[tid] + part[NH + tid] + part[2 * NH + tid] + part[3 * NH + tid]) * inv;
    __syncthreads();

    #pragma unroll 1
    for (int i = 0; i < 13; i++) {
        const int j0 = w * 25 + 2 * i;
        const bool has1 = (2 * i + 1 < 25);
        const int j1 = has1 ? j0 + 1 : j0;
        const float* r0 = Wih + (size_t)j0 * (NH + 1) + 1;
        const float* r1 = Wih + (size_t)j1 * (NH + 1) + 1;
        float s0 = 0.f, s1 = 0.f;
        #pragma unroll
        for (int k = l; k < NH; k += 32) {
            float c = ctxs[k];
            s0 = fmaf(c, r0[k], s0);
            s1 = fmaf(c, r1[k], s1);
        }
        s0 = warp_sum(s0);
        s1 = warp_sum(s1);
        if (l == 0) {
            gc[j0] = s0 + bih[j0] + g_hpre[b * NH4 + j0];
            if (has1) gc[j1] = s1 + bih[j1] + g_hpre[b * NH4 + j1];
        }
    }
    __syncthreads();

    const float b3v = b3[0];
    for (int st = 0; st < NSTEP; st++) {
        const float xv = xcur[0];
        if (tid < NH) {
            float gi = fmaf(xv, w0[tid], gc[tid]);
            float gf = fmaf(xv, w0[NH + tid], gc[NH + tid]);
            float gg = fmaf(xv, w0[2 * NH + tid], gc[2 * NH + tid]);
            float go = fmaf(xv, w0[3 * NH + tid], gc[3 * NH + tid]);
            float c  = sigm(gf) * c0s[tid] + sigm(gi) * tanhf(gg);
            buf0[tid] = fmaxf(sigm(go) * tanhf(c), 0.f);
        }
        __syncthreads();
        #pragma unroll
        for (int i = 0; i < 4; i++) {
            int j = w + 32 * i; int jj = min(j, 99);
            float s = 0.f;
            #pragma unroll
            for (int k = l; k < NH; k += 32) s = fmaf(W1s[jj * NH + k], buf0[k], s);
            s = warp_sum(s);
            if (l == 0 && j < 100) buf1[j] = fmaxf(s + b1s[j], 0.f);
        }
        __syncthreads();
        #pragma unroll
        for (int i = 0; i < 2; i++) {
            int j = w + 32 * i; int jj = min(j, 49);
            float s = 0.f;
            #pragma unroll
            for (int k = l; k < 100; k += 32) s = fmaf(W2s[jj * 100 + k], buf1[k], s);
            s = warp_sum(s);
            if (l == 0 && j < 50) buf2[j] = fmaxf(s + b2s[j], 0.f);
        }
        __syncthreads();
        if (w == 0) {
            float s = (l < 50) ? W3s[l] * buf2[l] : 0.f;
            if (l < 18) s = fmaf(W3s[l + 32], buf2[l + 32], s);
            s = warp_sum(s);
            if (l == 0) {
                float y = s + b3v;
                out[b * NSTEP + st] = y;
                xcur[0] = y;
            }
        }
        __syncthreads();
    }
}

// ============================================================================
extern "C" void kernel_launch(void* const* d_in, const int* in_sizes, int n_in,
                              void* d_out, int out_size) {
    const float* x   = (const float*)d_in[0];
    const float* h0  = (const float*)d_in[1];
    const float* c0  = (const float*)d_in[2];
    const float* enc = (const float*)d_in[3];
    const float* Wa  = (const float*)d_in[4];
    const float* ba  = (const float*)d_in[5];
    const float* Ua  = (const float*)d_in[6];
    const float* bua = (const float*)d_in[7];
    const float* Va  = (const float*)d_in[8];
    const float* bva = (const float*)d_in[9];
    const float* Wih = (const float*)d_in[10];
    const float* Whh = (const float*)d_in[11];
    const float* bih = (const float*)d_in[12];
    const float* bhh = (const float*)d_in[13];
    const float* W1  = (const float*)d_in[14];
    const float* b1  = (const float*)d_in[15];
    const float* W2  = (const float*)d_in[16];
    const float* b2  = (const float*)d_in[17];
    const float* W3  = (const float*)d_in[18];
    const float* b3  = (const float*)d_in[19];
    float* out = (float*)d_out;

    cudaFuncSetAttribute(k_pre, cudaFuncAttributeMaxDynamicSharedMemorySize,
                         (int)SMEM_PRE);
    cudaFuncSetAttribute(k_scores, cudaFuncAttributeMaxDynamicSharedMemorySize,
                         (int)SMEM_SC);
    cudaFuncSetAttribute(k_softdec, cudaFuncAttributeMaxDynamicSharedMemorySize,
                         (int)SMEM_DEC);

    k_pre<<<125, 256, SMEM_PRE>>>(h0, Wa, ba, Whh, bhh);
    k_scores<<<NCTA, 512, SMEM_SC>>>(enc, Ua, bua, Va, bva);
    k_softdec<<<NB, 1024, SMEM_DEC>>>(x, c0, Wih, bih,
                                      W1, b1, W2, b2, W3, b3, out);
}